// round 8
// baseline (speedup 1.0000x reference)
#include <cuda_runtime.h>
#include <cstdint>

#define BH   64
#define S    2048
#define RNK  64
#define D    64
#define NELEM (BH*S*RNK)

// 1 = modern JAX threefry_partitionable (default >= 0.4.30). Flip to 0 if rel_err ~O(1).
#define JAX_PARTITIONABLE 1

__device__ __align__(16) float g_L   [NELEM];
__device__ __align__(16) float g_Rp  [NELEM];
__device__ __align__(16) float g_ls  [NELEM];
__device__ __align__(16) float g_rs  [NELEM];
__device__ __align__(16) float g_dtmp[NELEM];
__device__ float g_invL[BH*S];
__device__ float g_invR[BH*RNK];
__device__ float g_rowdot[BH*RNK];
__device__ float g_pdot[BH*RNK*32];
__device__ float g_G [BH*RNK*RNK];
__device__ float g_H [BH*RNK*RNK];
__device__ float g_P [BH*RNK*D];
__device__ float g_RK[BH*RNK*D];
__device__ float g_W [BH*RNK*D];

__host__ __device__ inline void tf2x32(uint32_t k0, uint32_t k1,
                                       uint32_t x0, uint32_t x1,
                                       uint32_t* o0, uint32_t* o1) {
    uint32_t ks0 = k0, ks1 = k1, ks2 = k0 ^ k1 ^ 0x1BD11BDAu;
    x0 += ks0; x1 += ks1;
#define TF_RND(r) { x0 += x1; x1 = (x1 << (r)) | (x1 >> (32 - (r))); x1 ^= x0; }
    TF_RND(13) TF_RND(15) TF_RND(26) TF_RND(6)
    x0 += ks1; x1 += ks2 + 1u;
    TF_RND(17) TF_RND(29) TF_RND(16) TF_RND(24)
    x0 += ks2; x1 += ks0 + 2u;
    TF_RND(13) TF_RND(15) TF_RND(26) TF_RND(6)
    x0 += ks0; x1 += ks1 + 3u;
    TF_RND(17) TF_RND(29) TF_RND(16) TF_RND(24)
    x0 += ks1; x1 += ks2 + 4u;
    TF_RND(13) TF_RND(15) TF_RND(26) TF_RND(6)
    x0 += ks2; x1 += ks0 + 5u;
#undef TF_RND
    *o0 = x0; *o1 = x1;
}

__device__ inline float bits_to_unit(uint32_t bits) {
    return __uint_as_float((bits >> 9) | 0x3F800000u) - 1.0f;
}

__device__ inline uint32_t rbits(uint32_t ka, uint32_t kb, uint32_t idx) {
    uint32_t o0, o1;
#if JAX_PARTITIONABLE
    tf2x32(ka, kb, 0u, idx, &o0, &o1);
    return o0 ^ o1;
#else
    const uint32_t HN = NELEM / 2;
    if (idx < HN) { tf2x32(ka, kb, idx, idx + HN, &o0, &o1); return o0; }
    tf2x32(ka, kb, idx - HN, idx, &o0, &o1); return o1;
#endif
}

__global__ void k_init(uint32_t la, uint32_t lb, uint32_t ra, uint32_t rb) {
    int idx = blockIdx.x * blockDim.x + threadIdx.x;
    if (idx >= NELEM) return;
    float u = bits_to_unit(rbits(la, lb, (uint32_t)idx));
    g_L[idx] = 0.125f + (0.002f * u - 0.001f);
    u = bits_to_unit(rbits(ra, rb, (uint32_t)idx));
    g_Rp[idx] = 0.022097086912079608f + (0.002f * u - 0.001f);
}

// per-row (len 64) sphere + inv norm of L. grid(64,256) x 256
__global__ void k_prepL() {
    int bh = blockIdx.x;
    int w = threadIdx.x >> 5, lane = threadIdx.x & 31;
    int i = blockIdx.y * 8 + w;
    int base = bh * S * RNK + i * RNK;
    float v0 = g_L[base + lane], v1 = g_L[base + 32 + lane];
    float ss = v0 * v0 + v1 * v1;
    #pragma unroll
    for (int o = 16; o > 0; o >>= 1) ss += __shfl_xor_sync(0xffffffffu, ss, o);
    float n = sqrtf(ss);
    float inv = (n > 0.f) ? (1.0f / n) : 0.0f;
    g_ls[base + lane]      = (n > 0.f) ? v0 * inv : v0;
    g_ls[base + 32 + lane] = (n > 0.f) ? v1 * inv : v1;
    if (lane == 0) g_invL[bh * S + i] = inv;
}

// per-row (len 2048) sphere + inv norm of R. grid(64,64) x 256
__global__ void k_prepR() {
    int bh = blockIdx.x, j = blockIdx.y;
    int base = bh * RNK * S + j * S;
    int tid = threadIdx.x;
    float v[8]; float ss = 0.f;
    #pragma unroll
    for (int p = 0; p < 8; p++) { v[p] = g_Rp[base + p * 256 + tid]; ss += v[p] * v[p]; }
    #pragma unroll
    for (int o = 16; o > 0; o >>= 1) ss += __shfl_xor_sync(0xffffffffu, ss, o);
    __shared__ float red[8];
    if ((tid & 31) == 0) red[tid >> 5] = ss;
    __syncthreads();
    float n = sqrtf(red[0]+red[1]+red[2]+red[3]+red[4]+red[5]+red[6]+red[7]);
    float inv = (n > 0.f) ? (1.0f / n) : 0.0f;
    #pragma unroll
    for (int p = 0; p < 8; p++)
        g_rs[base + p * 256 + tid] = (n > 0.f) ? v[p] * inv : v[p];
    if (tid == 0) g_invR[bh * RNK + j] = inv;
}

// 64x64-out contractions over K=2048. mode 0:H 1:P 2:G 3:RK 4:W. grid(64,nmodes) x 256
__global__ void k_gemm64(const float* __restrict__ q, const float* __restrict__ kin,
                         const float* __restrict__ vin, int modebase) {
    __shared__ float Abuf[64 * 33];   // reused as [32][65]
    __shared__ float Bbuf[32 * 65];
    int bh = blockIdx.x, mode = modebase + blockIdx.y, tid = threadIdx.x;
    int ty = tid >> 4, tx = tid & 15;
    float acc[4][4];
    #pragma unroll
    for (int a = 0; a < 4; a++) { acc[a][0]=0.f; acc[a][1]=0.f; acc[a][2]=0.f; acc[a][3]=0.f; }

    if (mode <= 1) {
        const float* lsb = g_ls + bh * S * RNK;
        const float* qb  = q + bh * S * D;
        for (int k0 = 0; k0 < S; k0 += 32) {
            #pragma unroll
            for (int p = 0; p < 8; p++) {
                int e = p * 256 + tid, r0 = e >> 6, c = e & 63;
                float x = lsb[(k0 + r0) * RNK + c];
                Abuf[r0 * 65 + c] = x * x;
                if (mode == 1) Bbuf[r0 * 65 + c] = 0.125f * qb[(k0 + r0) * D + c];
            }
            __syncthreads();
            const float* Bp = (mode == 0) ? Abuf : Bbuf;
            #pragma unroll 4
            for (int i = 0; i < 32; i++) {
                float av[4], bv[4];
                #pragma unroll
                for (int a = 0; a < 4; a++) av[a] = Abuf[i * 65 + ty * 4 + a];
                #pragma unroll
                for (int b = 0; b < 4; b++) bv[b] = Bp[i * 65 + tx * 4 + b];
                #pragma unroll
                for (int a = 0; a < 4; a++)
                    #pragma unroll
                    for (int b = 0; b < 4; b++) acc[a][b] += av[a] * bv[b];
            }
            __syncthreads();
        }
    } else {
        const float* rsb = g_rs + bh * RNK * S;
        const float* src = (mode == 3) ? (kin + bh * S * D) : (vin + bh * S * D);
        for (int t0 = 0; t0 < S; t0 += 32) {
            #pragma unroll
            for (int p = 0; p < 8; p++) {
                int e = p * 256 + tid, m = e >> 5, tt = e & 31;
                float x = rsb[m * S + t0 + tt];
                Abuf[m * 33 + tt] = x * x;
            }
            if (mode >= 3) {
                #pragma unroll
                for (int p = 0; p < 8; p++) {
                    int e = p * 256 + tid, r0 = e >> 6, c = e & 63;
                    Bbuf[r0 * 65 + c] = src[(t0 + r0) * D + c];
                }
            }
            __syncthreads();
            #pragma unroll 4
            for (int tt = 0; tt < 32; tt++) {
                float av[4], bv[4];
                #pragma unroll
                for (int a = 0; a < 4; a++) av[a] = Abuf[(ty * 4 + a) * 33 + tt];
                if (mode == 2) {
                    #pragma unroll
                    for (int b = 0; b < 4; b++) bv[b] = Abuf[(tx * 4 + b) * 33 + tt];
                } else {
                    #pragma unroll
                    for (int b = 0; b < 4; b++) bv[b] = Bbuf[tt * 65 + tx * 4 + b];
                }
                #pragma unroll
                for (int a = 0; a < 4; a++)
                    #pragma unroll
                    for (int b = 0; b < 4; b++) acc[a][b] += av[a] * bv[b];
            }
            __syncthreads();
        }
    }
    float* out;
    switch (mode) { case 0: out = g_H; break; case 1: out = g_P; break;
                    case 2: out = g_G; break; case 3: out = g_RK; break;
                    default: out = g_W; break; }
    out += bh * 4096;
    #pragma unroll
    for (int a = 0; a < 4; a++)
        #pragma unroll
        for (int b = 0; b < 4; b++)
            out[(ty * 4 + a) * 64 + tx * 4 + b] = acc[a][b];
}

// d_left = lsq@G - (q/8)@RK^T ; PGD row update. grid(64,16) x 256
__global__ void k_updateL(const float* __restrict__ q) {
    __shared__ float Gs [64 * 65];
    __shared__ float RKs[64 * 65];
    int bh = blockIdx.x;
    for (int e = threadIdx.x; e < 4096; e += 256) {
        int r0 = e >> 6, c = e & 63;
        Gs [r0 * 65 + c] = g_G [bh * 4096 + e];
        RKs[r0 * 65 + c] = g_RK[bh * 4096 + e];
    }
    __syncthreads();
    int w = threadIdx.x >> 5, lane = threadIdx.x & 31;
    for (int g = 0; g < 4; g++) {
        int i0 = blockIdx.y * 128 + w * 16 + g * 4;
        float ls0[4], ls1[4], lq0[4], lq1[4], qv0[4], qv1[4], a0[4], a1[4], b0[4], b1[4];
        #pragma unroll
        for (int r = 0; r < 4; r++) {
            int base = bh * S * RNK + (i0 + r) * RNK;
            ls0[r] = g_ls[base + lane]; ls1[r] = g_ls[base + 32 + lane];
            lq0[r] = ls0[r] * ls0[r];   lq1[r] = ls1[r] * ls1[r];
            qv0[r] = 0.125f * q[bh * S * D + (i0 + r) * D + lane];
            qv1[r] = 0.125f * q[bh * S * D + (i0 + r) * D + 32 + lane];
            a0[r] = 0.f; a1[r] = 0.f; b0[r] = 0.f; b1[r] = 0.f;
        }
        #pragma unroll 4
        for (int m = 0; m < 64; m++) {
            float x0 = Gs[m * 65 + lane], x1 = Gs[m * 65 + 32 + lane];
            #pragma unroll
            for (int r = 0; r < 4; r++) {
                float lv = (m < 32) ? __shfl_sync(0xffffffffu, lq0[r], m)
                                    : __shfl_sync(0xffffffffu, lq1[r], m - 32);
                a0[r] += lv * x0; a1[r] += lv * x1;
            }
        }
        #pragma unroll 4
        for (int d = 0; d < 64; d++) {
            float y0 = RKs[lane * 65 + d], y1 = RKs[(lane + 32) * 65 + d];
            #pragma unroll
            for (int r = 0; r < 4; r++) {
                float qq = (d < 32) ? __shfl_sync(0xffffffffu, qv0[r], d)
                                    : __shfl_sync(0xffffffffu, qv1[r], d - 32);
                b0[r] += qq * y0; b1[r] += qq * y1;
            }
        }
        #pragma unroll
        for (int r = 0; r < 4; r++) {
            int i = i0 + r, base = bh * S * RNK + i * RNK;
            float dl0 = (a0[r] - b0[r]) * 2.0f * ls0[r];
            float dl1 = (a1[r] - b1[r]) * 2.0f * ls1[r];
            float c = ls0[r] * dl0 + ls1[r] * dl1;
            #pragma unroll
            for (int o = 16; o > 0; o >>= 1) c += __shfl_xor_sync(0xffffffffu, c, o);
            float inv = g_invL[bh * S + i];
            g_L[base + lane]      -= inv * (dl0 - ls0[r] * c);
            g_L[base + 32 + lane] -= inv * (dl1 - ls1[r] * c);
        }
    }
}

// dtmp = 2*rs*(H@rsq - P@kT) + deterministic partial row dots. grid(64,32) x 256
__global__ void k_updateRa(const float* __restrict__ kin) {
    __shared__ float rq[64 * 65];
    __shared__ float ks[64 * 65];
    int bh = blockIdx.x, t0 = blockIdx.y * 64;
    const float* rsb = g_rs + bh * RNK * S;
    for (int e = threadIdx.x; e < 4096; e += 256) {
        int r0 = e >> 6, c = e & 63;
        float x = rsb[r0 * S + t0 + c];
        rq[r0 * 65 + c] = x * x;
        ks[r0 * 65 + c] = kin[bh * S * D + (t0 + r0) * D + c];
    }
    __syncthreads();
    int w = threadIdx.x >> 5, lane = threadIdx.x & 31;
    for (int g = 0; g < 2; g++) {
        int jb = w * 8 + g * 4;
        float h0[4], h1[4], p0[4], p1[4], a0[4], a1[4];
        #pragma unroll
        for (int r = 0; r < 4; r++) {
            int j = jb + r;
            h0[r] = g_H[bh * 4096 + j * 64 + lane];
            h1[r] = g_H[bh * 4096 + j * 64 + 32 + lane];
            p0[r] = g_P[bh * 4096 + j * 64 + lane];
            p1[r] = g_P[bh * 4096 + j * 64 + 32 + lane];
            a0[r] = 0.f; a1[r] = 0.f;
        }
        #pragma unroll 4
        for (int m = 0; m < 64; m++) {
            float x0 = rq[m * 65 + lane], x1 = rq[m * 65 + 32 + lane];
            #pragma unroll
            for (int r = 0; r < 4; r++) {
                float hv = (m < 32) ? __shfl_sync(0xffffffffu, h0[r], m)
                                    : __shfl_sync(0xffffffffu, h1[r], m - 32);
                a0[r] += hv * x0; a1[r] += hv * x1;
            }
        }
        #pragma unroll 4
        for (int d = 0; d < 64; d++) {
            float y0 = ks[lane * 65 + d], y1 = ks[(lane + 32) * 65 + d];
            #pragma unroll
            for (int r = 0; r < 4; r++) {
                float pv = (d < 32) ? __shfl_sync(0xffffffffu, p0[r], d)
                                    : __shfl_sync(0xffffffffu, p1[r], d - 32);
                a0[r] -= pv * y0; a1[r] -= pv * y1;
            }
        }
        #pragma unroll
        for (int r = 0; r < 4; r++) {
            int j = jb + r, rbase = bh * RNK * S + j * S + t0;
            float rs0 = g_rs[rbase + lane], rs1 = g_rs[rbase + 32 + lane];
            float dt0 = a0[r] * 2.0f * rs0, dt1 = a1[r] * 2.0f * rs1;
            g_dtmp[rbase + lane] = dt0;
            g_dtmp[rbase + 32 + lane] = dt1;
            float pd = rs0 * dt0 + rs1 * dt1;
            #pragma unroll
            for (int o = 16; o > 0; o >>= 1) pd += __shfl_xor_sync(0xffffffffu, pd, o);
            if (lane == 0) g_pdot[(bh * RNK + j) * 32 + blockIdx.y] = pd;
        }
    }
}

__global__ void k_rowdot() {
    int r = blockIdx.x * blockDim.x + threadIdx.x;
    if (r < BH * RNK) {
        float s = 0.f;
        #pragma unroll
        for (int p = 0; p < 32; p++) s += g_pdot[r * 32 + p];
        g_rowdot[r] = s;
    }
}

__global__ void k_updateRb() {
    int idx = blockIdx.x * blockDim.x + threadIdx.x;  // float4 index
    if (idx >= NELEM / 4) return;
    int row = (idx * 4) >> 11;
    float inv = g_invR[row], rd = g_rowdot[row];
    float4 dt = ((const float4*)g_dtmp)[idx];
    float4 rs = ((const float4*)g_rs)[idx];
    float4 Rv = ((float4*)g_Rp)[idx];
    Rv.x -= inv * (dt.x - rs.x * rd);
    Rv.y -= inv * (dt.y - rs.y * rd);
    Rv.z -= inv * (dt.z - rs.z * rd);
    Rv.w -= inv * (dt.w - rs.w * rd);
    ((float4*)g_Rp)[idx] = Rv;
}

// out = lsq^2 @ W. grid(64,16) x 256
__global__ void k_out(float* __restrict__ out) {
    __shared__ float Ws[64 * 65];
    int bh = blockIdx.x;
    for (int e = threadIdx.x; e < 4096; e += 256)
        Ws[(e >> 6) * 65 + (e & 63)] = g_W[bh * 4096 + e];
    __syncthreads();
    int w = threadIdx.x >> 5, lane = threadIdx.x & 31;
    for (int g = 0; g < 4; g++) {
        int i0 = blockIdx.y * 128 + w * 16 + g * 4;
        float lq0[4], lq1[4], o0[4], o1[4];
        #pragma unroll
        for (int r = 0; r < 4; r++) {
            int base = bh * S * RNK + (i0 + r) * RNK;
            float a = g_ls[base + lane], b = g_ls[base + 32 + lane];
            lq0[r] = a * a; lq1[r] = b * b;
            o0[r] = 0.f; o1[r] = 0.f;
        }
        #pragma unroll 4
        for (int j = 0; j < 64; j++) {
            float x0 = Ws[j * 65 + lane], x1 = Ws[j * 65 + 32 + lane];
            #pragma unroll
            for (int r = 0; r < 4; r++) {
                float lv = (j < 32) ? __shfl_sync(0xffffffffu, lq0[r], j)
                                    : __shfl_sync(0xffffffffu, lq1[r], j - 32);
                o0[r] += lv * x0; o1[r] += lv * x1;
            }
        }
        #pragma unroll
        for (int r = 0; r < 4; r++) {
            int ob = bh * S * D + (i0 + r) * D;
            out[ob + lane]      = o0[r];
            out[ob + 32 + lane] = o1[r];
        }
    }
}

extern "C" void kernel_launch(void* const* d_in, const int* in_sizes, int n_in,
                              void* d_out, int out_size) {
    const float* q = (const float*)d_in[0];
    const float* k = (const float*)d_in[1];
    const float* v = (const float*)d_in[2];
    float* out = (float*)d_out;

    // split(key(42)) on host
    uint32_t k1a, k1b, k2a, k2b;
#if JAX_PARTITIONABLE
    tf2x32(0u, 42u, 0u, 0u, &k1a, &k1b);
    tf2x32(0u, 42u, 0u, 1u, &k2a, &k2b);
#else
    { uint32_t a0, b0, a1, b1;
      tf2x32(0u, 42u, 0u, 2u, &a0, &b0);
      tf2x32(0u, 42u, 1u, 3u, &a1, &b1);
      k1a = a0; k1b = a1; k2a = b0; k2b = b1; }
#endif

    k_init<<<NELEM / 256, 256>>>(k1a, k1b, k2a, k2b);
    for (int step = 0; step < 8; step++) {
        k_prepL<<<dim3(BH, 256), 256>>>();
        k_prepR<<<dim3(BH, 64), 256>>>();
        k_gemm64<<<dim3(BH, 4), 256>>>(q, k, v, 0);   // H, P, G, RK
        k_updateL<<<dim3(BH, 16), 256>>>(q);
        k_updateRa<<<dim3(BH, 32), 256>>>(k);
        k_rowdot<<<16, 256>>>();
        k_updateRb<<<NELEM / 4 / 256, 256>>>();
    }
    k_prepL<<<dim3(BH, 256), 256>>>();
    k_prepR<<<dim3(BH, 64), 256>>>();
    k_gemm64<<<dim3(BH, 1), 256>>>(q, k, v, 4);       // W = rsq @ value
    k_out<<<dim3(BH, 16), 256>>>(out);
}